// round 3
// baseline (speedup 1.0000x reference)
#include <cuda_runtime.h>
#include <math.h>

// ---------------------------------------------------------------------------
// Mamba (8 layers), fp32 baseline.
//   per layer: rmsnorm -> in_proj GEMM -> causal conv+silu -> x_proj GEMM
//              -> dt_proj GEMM -> softplus -> selective scan (+gate, +Dskip)
//              -> out_proj GEMM (+residual)
//   final rmsnorm -> d_out
// ---------------------------------------------------------------------------

namespace {
constexpr int NL   = 8;
constexpr int DM   = 768;      // hidden
constexpr int ED   = 1536;     // intermediate
constexpr int NS   = 16;       // state dim
constexpr int KC   = 4;        // conv kernel
constexpr int DTRK = 48;       // dt rank
constexpr int BB   = 2;
constexpr int LL   = 2048;
constexpr int M    = BB * LL;  // 4096 tokens
constexpr int SSMC = DTRK + 2 * NS;  // 80
constexpr float EPS = 1e-5f;
}

// ------------------------- scratch (static device) -------------------------
__device__ float g_h   [M * DM];
__device__ float g_hn  [M * DM];
__device__ float g_proj[M * 2 * ED];
__device__ float g_u   [M * ED];
__device__ float g_ssm [M * SSMC];
__device__ float g_dt  [M * ED];
__device__ float g_y   [M * ED];

// ------------------------------- RMSNorm -----------------------------------
__global__ void rmsnorm_kernel(const float* __restrict__ h,
                               const float* __restrict__ w,
                               float* __restrict__ out) {
    const int m = blockIdx.x;
    const float* row = h + (size_t)m * DM;
    float s = 0.f;
    for (int i = threadIdx.x; i < DM; i += 256) {
        float v = row[i];
        s = fmaf(v, v, s);
    }
    #pragma unroll
    for (int o = 16; o; o >>= 1) s += __shfl_xor_sync(0xffffffffu, s, o);
    __shared__ float red[8];
    if ((threadIdx.x & 31) == 0) red[threadIdx.x >> 5] = s;
    __syncthreads();
    if (threadIdx.x == 0) {
        float t = 0.f;
        #pragma unroll
        for (int i = 0; i < 8; i++) t += red[i];
        red[0] = rsqrtf(t * (1.0f / DM) + EPS);
    }
    __syncthreads();
    const float inv = red[0];
    float* orow = out + (size_t)m * DM;
    for (int i = threadIdx.x; i < DM; i += 256) orow[i] = row[i] * inv * w[i];
}

// ------------------------------- SGEMM (NT) --------------------------------
// C[m,n] = sum_k A[m,k] * W[n,k]  (+ Res[m,n] if ADD_RES)
// A row stride = lda; W row stride = Kk; C/Res row stride = Nn.
// Requires: M % BM_ == 0, Kk % BK_ == 0 (true for all call sites).
template <int BM_, int BN_, int BK_, int TM_, int TN_, bool ADD_RES>
__global__ void __launch_bounds__((BM_ / TM_) * (BN_ / TN_))
gemm_nt(const float* __restrict__ A, int lda,
        const float* __restrict__ W,
        const float* __restrict__ Res,
        float* __restrict__ C,
        int Nn, int Kk) {
    constexpr int NT = (BM_ / TM_) * (BN_ / TN_);
    constexpr int KV = BK_ / 4;                 // float4s per K-slab row
    __shared__ float As[BK_][BM_ + 4];
    __shared__ float Ws[BK_][BN_ + 4];

    const int tid  = threadIdx.x;
    const int bm   = blockIdx.y * BM_;
    const int bn   = blockIdx.x * BN_;
    const int trow = (tid / (BN_ / TN_)) * TM_;
    const int tcol = (tid % (BN_ / TN_)) * TN_;

    float acc[TM_][TN_];
    #pragma unroll
    for (int i = 0; i < TM_; i++)
        #pragma unroll
        for (int j = 0; j < TN_; j++) acc[i][j] = 0.f;

    for (int k0 = 0; k0 < Kk; k0 += BK_) {
        #pragma unroll
        for (int it = 0; it < BM_ * KV / NT; ++it) {
            int i  = tid + it * NT;
            int r  = i / KV;
            int c4 = (i % KV) * 4;
            float4 v = *reinterpret_cast<const float4*>(
                &A[(size_t)(bm + r) * lda + k0 + c4]);
            As[c4 + 0][r] = v.x; As[c4 + 1][r] = v.y;
            As[c4 + 2][r] = v.z; As[c4 + 3][r] = v.w;
        }
        #pragma unroll
        for (int it = 0; it < BN_ * KV / NT; ++it) {
            int i  = tid + it * NT;
            int r  = i / KV;
            int c4 = (i % KV) * 4;
            float4 v = make_float4(0.f, 0.f, 0.f, 0.f);
            if (bn + r < Nn)
                v = *reinterpret_cast<const float4*>(
                    &W[(size_t)(bn + r) * Kk + k0 + c4]);
            Ws[c4 + 0][r] = v.x; Ws[c4 + 1][r] = v.y;
            Ws[c4 + 2][r] = v.z; Ws[c4 + 3][r] = v.w;
        }
        __syncthreads();
        #pragma unroll
        for (int kk = 0; kk < BK_; ++kk) {
            float ra[TM_], rw[TN_];
            #pragma unroll
            for (int i = 0; i < TM_; i++) ra[i] = As[kk][trow + i];
            #pragma unroll
            for (int j = 0; j < TN_; j++) rw[j] = Ws[kk][tcol + j];
            #pragma unroll
            for (int i = 0; i < TM_; i++)
                #pragma unroll
                for (int j = 0; j < TN_; j++)
                    acc[i][j] = fmaf(ra[i], rw[j], acc[i][j]);
        }
        __syncthreads();
    }

    #pragma unroll
    for (int i = 0; i < TM_; i++) {
        const int gm = bm + trow + i;
        #pragma unroll
        for (int j = 0; j < TN_; j++) {
            const int gn = bn + tcol + j;
            if (gn < Nn) {
                float v = acc[i][j];
                if (ADD_RES) v += Res[(size_t)gm * Nn + gn];
                C[(size_t)gm * Nn + gn] = v;
            }
        }
    }
}

// ------------------------ causal depthwise conv + silu ---------------------
// u[m,e] = silu( cb[e] + sum_{k=0..3} cw[e,k] * proj[m-3+k, e] )  (t>=0 only)
__global__ void conv_silu_kernel(const float* __restrict__ proj,
                                 const float* __restrict__ cw,
                                 const float* __restrict__ cb,
                                 float* __restrict__ u) {
    const int idx = blockIdx.x * blockDim.x + threadIdx.x;
    if (idx >= M * ED) return;
    const int e = idx % ED;
    const int m = idx / ED;
    const int t = m % LL;

    const float w0 = cw[e * 4 + 0], w1 = cw[e * 4 + 1];
    const float w2 = cw[e * 4 + 2], w3 = cw[e * 4 + 3];
    const float* col = proj + (size_t)m * (2 * ED) + e;
    float acc = cb[e];
    acc = fmaf(w3, col[0], acc);
    if (t >= 1) acc = fmaf(w2, col[-(ptrdiff_t)(2 * ED)], acc);
    if (t >= 2) acc = fmaf(w1, col[-(ptrdiff_t)(4 * ED)], acc);
    if (t >= 3) acc = fmaf(w0, col[-(ptrdiff_t)(6 * ED)], acc);
    u[idx] = acc / (1.f + __expf(-acc));   // silu
}

// --------------------------- bias + softplus (dt) --------------------------
__global__ void softplus_kernel(float* __restrict__ dt,
                                const float* __restrict__ dtb) {
    const int idx = blockIdx.x * blockDim.x + threadIdx.x;
    if (idx >= M * ED) return;
    const int e = idx % ED;
    const float x = dt[idx] + dtb[e];
    // jax.nn.softplus(x) = max(x,0) + log1p(exp(-|x|))
    dt[idx] = fmaxf(x, 0.f) + log1pf(__expf(-fabsf(x)));
}

// ------------------------------ selective scan -----------------------------
// One block handles 32 channels (e) of one batch; each channel is split over
// 4 lanes (4 states each) and partial y is combined by shuffles.
// Epilogue fused: y = (scan_y + u*Dskip) * silu(gate).
namespace { constexpr int SCAN_T = 16; }

__global__ void __launch_bounds__(128)
scan_kernel(const float* __restrict__ dt, const float* __restrict__ u,
            const float* __restrict__ ssm, const float* __restrict__ proj,
            const float* __restrict__ A_log_l, const float* __restrict__ Dsk_l,
            float* __restrict__ y) {
    const int b   = blockIdx.y;
    const int e0  = blockIdx.x * 32;
    const int tx  = threadIdx.x;
    const int el  = tx >> 2;     // 0..31: channel within block
    const int sub = tx & 3;      // state group (4 states each)
    const int e   = e0 + el;

    __shared__ float sdt[SCAN_T][32];
    __shared__ float su [SCAN_T][32];
    __shared__ float sg [SCAN_T][32];
    __shared__ float sB [SCAN_T][NS];
    __shared__ float sC [SCAN_T][NS];

    float Ac[4];
    #pragma unroll
    for (int j = 0; j < 4; j++)
        Ac[j] = -expf(A_log_l[e * NS + sub * 4 + j]);
    const float Dk = Dsk_l[e];

    float st[4] = {0.f, 0.f, 0.f, 0.f};

    for (int t0 = 0; t0 < LL; t0 += SCAN_T) {
        __syncthreads();
        for (int i = tx; i < SCAN_T * 32; i += 128) {
            const int t = i >> 5, c = i & 31;
            const size_t m = (size_t)(b * LL + t0 + t);
            sdt[t][c] = dt[m * ED + e0 + c];
            su [t][c] = u [m * ED + e0 + c];
            sg [t][c] = proj[m * (2 * ED) + ED + e0 + c];
        }
        for (int i = tx; i < SCAN_T * NS; i += 128) {
            const int t = i >> 4, n = i & (NS - 1);
            const size_t base = (size_t)(b * LL + t0 + t) * SSMC;
            sB[t][n] = ssm[base + DTRK + n];
            sC[t][n] = ssm[base + DTRK + NS + n];
        }
        __syncthreads();
        #pragma unroll 4
        for (int t = 0; t < SCAN_T; t++) {
            const float dtv = sdt[t][el];
            const float uv  = su[t][el];
            const float dtu = dtv * uv;
            float yv = 0.f;
            #pragma unroll
            for (int j = 0; j < 4; j++) {
                const float dA = __expf(dtv * Ac[j]);
                st[j] = fmaf(st[j], dA, dtu * sB[t][sub * 4 + j]);
                yv = fmaf(st[j], sC[t][sub * 4 + j], yv);
            }
            yv += __shfl_xor_sync(0xffffffffu, yv, 1);
            yv += __shfl_xor_sync(0xffffffffu, yv, 2);
            if (sub == 0) {
                const float g   = sg[t][el];
                const float sil = g / (1.f + __expf(-g));
                y[((size_t)(b * LL + t0 + t)) * ED + e] = (yv + uv * Dk) * sil;
            }
        }
    }
}

// -------------------------------- launcher ---------------------------------
extern "C" void kernel_launch(void* const* d_in, const int* in_sizes, int n_in,
                              void* d_out, int out_size) {
    (void)in_sizes; (void)n_in; (void)out_size;
    const float* x      = (const float*)d_in[0];
    const float* norm_w = (const float*)d_in[1];
    const float* in_w   = (const float*)d_in[2];
    const float* conv_w = (const float*)d_in[3];
    const float* conv_b = (const float*)d_in[4];
    const float* xw     = (const float*)d_in[5];
    const float* dtw    = (const float*)d_in[6];
    const float* dtb    = (const float*)d_in[7];
    const float* A_log  = (const float*)d_in[8];
    const float* Dsk    = (const float*)d_in[9];
    const float* ow     = (const float*)d_in[10];
    const float* fnw    = (const float*)d_in[11];
    float* out = (float*)d_out;

    float *h, *hn, *proj, *u, *ssm, *dt, *y;
    cudaGetSymbolAddress((void**)&h,    g_h);
    cudaGetSymbolAddress((void**)&hn,   g_hn);
    cudaGetSymbolAddress((void**)&proj, g_proj);
    cudaGetSymbolAddress((void**)&u,    g_u);
    cudaGetSymbolAddress((void**)&ssm,  g_ssm);
    cudaGetSymbolAddress((void**)&dt,   g_dt);
    cudaGetSymbolAddress((void**)&y,    g_y);

    cudaMemcpyAsync(h, x, sizeof(float) * (size_t)M * DM,
                    cudaMemcpyDeviceToDevice);

    const int NE = M * ED;
    for (int l = 0; l < NL; l++) {
        // 1) pre-norm
        rmsnorm_kernel<<<M, 256>>>(h, norm_w + l * DM, hn);
        // 2) in_proj: (M x DM) @ (2E x DM)^T -> proj (M x 2E)
        gemm_nt<128, 128, 16, 8, 8, false>
            <<<dim3(2 * ED / 128, M / 128), 256>>>(
                hn, DM, in_w + (size_t)l * 2 * ED * DM, nullptr, proj,
                2 * ED, DM);
        // 3) causal conv + silu on first E columns of proj -> u
        conv_silu_kernel<<<(NE + 255) / 256, 256>>>(
            proj, conv_w + l * ED * KC, conv_b + l * ED, u);
        // 4) x_proj: (M x E) @ (80 x E)^T -> ssm (M x 80)
        gemm_nt<64, 64, 16, 4, 4, false>
            <<<dim3((SSMC + 63) / 64, M / 64), 256>>>(
                u, ED, xw + (size_t)l * SSMC * ED, nullptr, ssm, SSMC, ED);
        // 5) dt_proj: (M x 48 view of ssm) @ (E x 48)^T -> dt (M x E)
        gemm_nt<128, 128, 16, 8, 8, false>
            <<<dim3(ED / 128, M / 128), 256>>>(
                ssm, SSMC, dtw + (size_t)l * ED * DTRK, nullptr, dt,
                ED, DTRK);
        // 6) + bias, softplus (in place)
        softplus_kernel<<<(NE + 255) / 256, 256>>>(dt, dtb + l * ED);
        // 7) selective scan + Dskip + gate -> y
        scan_kernel<<<dim3(ED / 32, BB), 128>>>(
            dt, u, ssm, proj, A_log + (size_t)l * ED * NS, Dsk + l * ED, y);
        // 8) out_proj + residual: h = h + y @ ow^T
        gemm_nt<128, 128, 16, 8, 8, true>
            <<<dim3(DM / 128, M / 128), 256>>>(
                y, ED, ow + (size_t)l * DM * ED, h, h, DM, ED);
    }
    // final norm
    rmsnorm_kernel<<<M, 256>>>(h, fnw, out);
}

// round 5
// speedup vs baseline: 1.3089x; 1.3089x over previous
#include <cuda_runtime.h>
#include <cuda_bf16.h>
#include <math.h>
#include <stdint.h>

typedef __nv_bfloat16 bf16;

namespace {
constexpr int NL = 8, DM = 768, ED = 1536, NS = 16, DTRK = 48, BB = 2, LL = 2048;
constexpr int M    = BB * LL;          // 4096
constexpr int SSMC = DTRK + 2 * NS;    // 80
constexpr int KPAD = 64;               // padded dt rank
constexpr float EPS = 1e-5f;
// GEMM tiling
constexpr int RSB   = 80;                       // SMEM row stride in bytes (40 bf16)
constexpr int TILEB = 128 * RSB;                // one split tile = 10240 B
constexpr int STB   = 4 * TILEB;                // stage = Ah,Al,Bh,Bl = 40960 B
constexpr int GEMM_DSMEM = 3 * STB;             // 122880 B
}

// ------------------------- scratch (static device) -------------------------
__device__ float g_h   [M * DM];
__device__ float g_proj[M * 2 * ED];
__device__ float g_u   [M * ED];
__device__ float g_ssm [M * SSMC];
__device__ float g_dt  [M * ED];
__device__ __align__(16) bf16 g_hn_h[M * DM],  g_hn_l[M * DM];
__device__ __align__(16) bf16 g_u_h [M * ED],  g_u_l [M * ED];
__device__ __align__(16) bf16 g_di_h[M * KPAD], g_di_l[M * KPAD];
__device__ __align__(16) bf16 g_y_h [M * ED],  g_y_l [M * ED];
__device__ __align__(16) bf16 g_wi_h[NL * 2 * ED * DM], g_wi_l[NL * 2 * ED * DM];
__device__ __align__(16) bf16 g_wx_h[NL * SSMC * ED],   g_wx_l[NL * SSMC * ED];
__device__ __align__(16) bf16 g_wd_h[NL * ED * KPAD],   g_wd_l[NL * ED * KPAD];
__device__ __align__(16) bf16 g_wo_h[NL * DM * ED],     g_wo_l[NL * DM * ED];

// ------------------------------ tiny helpers -------------------------------
__device__ __forceinline__ void fsplit(float v, bf16& h, bf16& l) {
    h = __float2bfloat16(v);
    l = __float2bfloat16(v - __bfloat162float(h));
}
__device__ __forceinline__ uint32_t smem_u32(const void* p) {
    return (uint32_t)__cvta_generic_to_shared(p);
}
__device__ __forceinline__ void cp16(uint32_t dst, const bf16* src) {
    asm volatile("cp.async.cg.shared.global [%0], [%1], 16;"
                 :: "r"(dst), "l"(src));
}
__device__ __forceinline__ void ldsm_x4(uint32_t* r, uint32_t addr) {
    asm volatile("ldmatrix.sync.aligned.m8n8.x4.shared.b16 {%0,%1,%2,%3}, [%4];"
                 : "=r"(r[0]), "=r"(r[1]), "=r"(r[2]), "=r"(r[3]) : "r"(addr));
}
__device__ __forceinline__ void mma16816(float* d, const uint32_t* a,
                                         uint32_t b0, uint32_t b1) {
    asm volatile(
        "mma.sync.aligned.m16n8k16.row.col.f32.bf16.bf16.f32 "
        "{%0,%1,%2,%3}, {%4,%5,%6,%7}, {%8,%9}, {%0,%1,%2,%3};"
        : "+f"(d[0]), "+f"(d[1]), "+f"(d[2]), "+f"(d[3])
        : "r"(a[0]), "r"(a[1]), "r"(a[2]), "r"(a[3]), "r"(b0), "r"(b1));
}

// ----------------------------- split converts ------------------------------
__global__ void split_arr(const float* __restrict__ w, bf16* __restrict__ h,
                          bf16* __restrict__ l, int n) {
    int i = blockIdx.x * 256 + threadIdx.x;
    if (i < n) { bf16 a, b; fsplit(w[i], a, b); h[i] = a; l[i] = b; }
}
// dt_proj weight: [NL*ED][48] -> [NL*ED][64] zero-padded
__global__ void split_dtw(const float* __restrict__ w, bf16* __restrict__ h,
                          bf16* __restrict__ l) {
    int i = blockIdx.x * 256 + threadIdx.x;
    if (i >= NL * ED * KPAD) return;
    int r = i & 63, e = i >> 6;
    float v = (r < DTRK) ? w[e * DTRK + r] : 0.f;
    bf16 a, b; fsplit(v, a, b); h[i] = a; l[i] = b;
}

// ------------------------------- RMSNorm -----------------------------------
template <bool SPLIT>
__global__ void rmsnorm_kernel(const float* __restrict__ h,
                               const float* __restrict__ w,
                               float* __restrict__ outf,
                               bf16* __restrict__ outh, bf16* __restrict__ outl) {
    const int m = blockIdx.x;
    const float* row = h + (size_t)m * DM;
    float s = 0.f;
    for (int i = threadIdx.x; i < DM; i += 256) { float v = row[i]; s = fmaf(v, v, s); }
    #pragma unroll
    for (int o = 16; o; o >>= 1) s += __shfl_xor_sync(0xffffffffu, s, o);
    __shared__ float red[8];
    if ((threadIdx.x & 31) == 0) red[threadIdx.x >> 5] = s;
    __syncthreads();
    if (threadIdx.x == 0) {
        float t = 0.f;
        #pragma unroll
        for (int i = 0; i < 8; i++) t += red[i];
        red[0] = rsqrtf(t * (1.0f / DM) + EPS);
    }
    __syncthreads();
    const float inv = red[0];
    for (int i = threadIdx.x; i < DM; i += 256) {
        float v = row[i] * inv * w[i];
        if (SPLIT) {
            bf16 a, b; fsplit(v, a, b);
            outh[(size_t)m * DM + i] = a; outl[(size_t)m * DM + i] = b;
        } else {
            outf[(size_t)m * DM + i] = v;
        }
    }
}

// ------------------------ causal depthwise conv + silu ---------------------
__global__ void conv_silu_kernel(const float* __restrict__ proj,
                                 const float* __restrict__ cw,
                                 const float* __restrict__ cb,
                                 float* __restrict__ u,
                                 bf16* __restrict__ uh, bf16* __restrict__ ul) {
    const int idx = blockIdx.x * blockDim.x + threadIdx.x;
    if (idx >= M * ED) return;
    const int e = idx % ED;
    const int m = idx / ED;
    const int t = m % LL;
    const float w0 = cw[e * 4 + 0], w1 = cw[e * 4 + 1];
    const float w2 = cw[e * 4 + 2], w3 = cw[e * 4 + 3];
    const float* col = proj + (size_t)m * (2 * ED) + e;
    float acc = cb[e];
    acc = fmaf(w3, col[0], acc);
    if (t >= 1) acc = fmaf(w2, col[-(ptrdiff_t)(2 * ED)], acc);
    if (t >= 2) acc = fmaf(w1, col[-(ptrdiff_t)(4 * ED)], acc);
    if (t >= 3) acc = fmaf(w0, col[-(ptrdiff_t)(6 * ED)], acc);
    float v = acc / (1.f + __expf(-acc));
    u[idx] = v;
    bf16 a, b; fsplit(v, a, b);
    uh[idx] = a; ul[idx] = b;
}

// ------------------------------ selective scan -----------------------------
namespace { constexpr int SCAN_T = 16; }

__global__ void __launch_bounds__(128)
scan_kernel(const float* __restrict__ dt, const float* __restrict__ u,
            const float* __restrict__ ssm, const float* __restrict__ proj,
            const float* __restrict__ A_log_l, const float* __restrict__ Dsk_l,
            bf16* __restrict__ yh, bf16* __restrict__ yl) {
    const int b  = blockIdx.y;
    const int e0 = blockIdx.x * 32;
    const int tx = threadIdx.x;
    const int el = tx >> 2, sub = tx & 3;
    const int e  = e0 + el;

    __shared__ float sdt[SCAN_T][32];
    __shared__ float su [SCAN_T][32];
    __shared__ float sg [SCAN_T][32];
    __shared__ float sB [SCAN_T][NS];
    __shared__ float sC [SCAN_T][NS];

    float Ac[4];
    #pragma unroll
    for (int j = 0; j < 4; j++) Ac[j] = -expf(A_log_l[e * NS + sub * 4 + j]);
    const float Dk = Dsk_l[e];
    float st[4] = {0.f, 0.f, 0.f, 0.f};

    for (int t0 = 0; t0 < LL; t0 += SCAN_T) {
        __syncthreads();
        for (int i = tx; i < SCAN_T * 32; i += 128) {
            const int t = i >> 5, c = i & 31;
            const size_t m = (size_t)(b * LL + t0 + t);
            sdt[t][c] = dt[m * ED + e0 + c];
            su [t][c] = u [m * ED + e0 + c];
            sg [t][c] = proj[m * (2 * ED) + ED + e0 + c];
        }
        for (int i = tx; i < SCAN_T * NS; i += 128) {
            const int t = i >> 4, n = i & (NS - 1);
            const size_t base = (size_t)(b * LL + t0 + t) * SSMC;
            sB[t][n] = ssm[base + DTRK + n];
            sC[t][n] = ssm[base + DTRK + NS + n];
        }
        __syncthreads();
        #pragma unroll 4
        for (int t = 0; t < SCAN_T; t++) {
            const float dtv = sdt[t][el];
            const float uv  = su[t][el];
            const float dtu = dtv * uv;
            float yv = 0.f;
            #pragma unroll
            for (int j = 0; j < 4; j++) {
                const float dA = __expf(dtv * Ac[j]);
                st[j] = fmaf(st[j], dA, dtu * sB[t][sub * 4 + j]);
                yv = fmaf(st[j], sC[t][sub * 4 + j], yv);
            }
            yv += __shfl_xor_sync(0xffffffffu, yv, 1);
            yv += __shfl_xor_sync(0xffffffffu, yv, 2);
            if (sub == 0) {
                const float g   = sg[t][el];
                const float sil = g / (1.f + __expf(-g));
                const float val = (yv + uv * Dk) * sil;
                const size_t oi = ((size_t)(b * LL + t0 + t)) * ED + e;
                bf16 a, bl; fsplit(val, a, bl);
                yh[oi] = a; yl[oi] = bl;
            }
        }
    }
}

// ------------------- tensor-core split-bf16 GEMM (mma.sync) ----------------
// C[M,Ntot] = A[M,K] x B[N,K]^T via AhBh + AhBl + AlBh.
// 128x128 tile/CTA, BK=32, 3-stage cp.async pipeline, 8 warps (2x4), warp
// tile 64x32 of m16n8k16 fragments.
// EPI: 0 = store fp32; 1 = C += result (residual, in place);
//      2 = softplus(result + aux[col]);  3 = x_proj (ssm fp32 + dt-in split)
template <int NB, int EPI>
__global__ void __launch_bounds__(256, 1)
gemm_mma(const bf16* __restrict__ Ah, const bf16* __restrict__ Al,
         const bf16* __restrict__ Bh, const bf16* __restrict__ Bl,
         int K, int Ntot,
         float* __restrict__ C, const float* __restrict__ aux,
         bf16* __restrict__ oh, bf16* __restrict__ ol) {
    extern __shared__ char dsm[];
    const uint32_t base = smem_u32(dsm);
    const int tid = threadIdx.x, wid = tid >> 5, lane = tid & 31;
    const int m0 = blockIdx.y * 128, n0 = blockIdx.x * 128;
    const int wrow = wid >> 2, wcol = wid & 3;

    float acc[4][4][4];
    #pragma unroll
    for (int i = 0; i < 4; i++)
        #pragma unroll
        for (int j = 0; j < 4; j++)
            #pragma unroll
            for (int c = 0; c < 4; c++) acc[i][j][c] = 0.f;

    const int S = K >> 5;   // k-stages of 32

    auto load_stage = [&](int st) {
        const int k0 = st << 5;
        const uint32_t sb = base + (st % 3) * STB;
        #pragma unroll
        for (int it = 0; it < 4; ++it) {        // A: 2 splits x 128 rows x 4 x16B
            int i = tid + it * 256;
            int split = i >> 9;
            int r = (i >> 2) & 127;
            int c = i & 3;
            const bf16* src = (split ? Al : Ah) + (size_t)(m0 + r) * K + k0 + c * 8;
            cp16(sb + split * TILEB + r * RSB + c * 16, src);
        }
        #pragma unroll
        for (int it = 0; it < 4; ++it) {        // B
            int i = tid + it * 256;
            int split = i >> 9;
            int r = (i >> 2) & 127;
            int c = i & 3;
            if (NB == 128 || r < NB) {
                const bf16* src = (split ? Bl : Bh) + (size_t)(n0 + r) * K + k0 + c * 8;
                cp16(sb + 2 * TILEB + split * TILEB + r * RSB + c * 16, src);
            }
        }
    };

    // lane-invariant parts of ldmatrix addresses (byte offsets within stage)
    uint32_t aoff[2][4], boff[2][2];
    {
        const int ar = wrow * 64 + (lane & 15);
        const int ak = (lane >> 4) * 16;                   // bytes
        #pragma unroll
        for (int sp = 0; sp < 2; ++sp)
            #pragma unroll
            for (int mf = 0; mf < 4; ++mf)
                aoff[sp][mf] = sp * TILEB + (ar + mf * 16) * RSB + ak;
        const int br = wcol * 32 + (lane & 7) + ((lane >> 4) << 3);
        const int bk = ((lane >> 3) & 1) * 16;             // bytes
        #pragma unroll
        for (int sp = 0; sp < 2; ++sp)
            #pragma unroll
            for (int nf2 = 0; nf2 < 2; ++nf2)
                boff[sp][nf2] = 2 * TILEB + sp * TILEB + (br + nf2 * 16) * RSB + bk;
    }

    // pipeline prologue
    for (int p = 0; p < 2; ++p) {
        if (p < S) load_stage(p);
        asm volatile("cp.async.commit_group;");
    }

    for (int s = 0; s < S; ++s) {
        if (s + 2 < S) load_stage(s + 2);
        asm volatile("cp.async.commit_group;");
        const int remain = S - 1 - s;
        if (remain == 0)      asm volatile("cp.async.wait_group 0;");
        else if (remain == 1) asm volatile("cp.async.wait_group 1;");
        else                  asm volatile("cp.async.wait_group 2;");
        __syncthreads();

        const uint32_t sb = base + (s % 3) * STB;
        #pragma unroll
        for (int ks = 0; ks < 2; ++ks) {
            const uint32_t kb = ks * 32;      // 16 bf16 = 32 bytes
            uint32_t a[2][4][4];
            #pragma unroll
            for (int sp = 0; sp < 2; ++sp)
                #pragma unroll
                for (int mf = 0; mf < 4; ++mf)
                    ldsm_x4(a[sp][mf], sb + aoff[sp][mf] + kb);
            uint32_t b[2][4][2];
            #pragma unroll
            for (int sp = 0; sp < 2; ++sp)
                #pragma unroll
                for (int nf2 = 0; nf2 < 2; ++nf2) {
                    uint32_t r[4];
                    ldsm_x4(r, sb + boff[sp][nf2] + kb);
                    b[sp][2 * nf2][0]     = r[0];
                    b[sp][2 * nf2][1]     = r[1];
                    b[sp][2 * nf2 + 1][0] = r[2];
                    b[sp][2 * nf2 + 1][1] = r[3];
                }
            #pragma unroll
            for (int mf = 0; mf < 4; ++mf)
                #pragma unroll
                for (int nf = 0; nf < 4; ++nf) {
                    mma16816(acc[mf][nf], a[0][mf], b[0][nf][0], b[0][nf][1]);
                    mma16816(acc[mf][nf], a[0][mf], b[1][nf][0], b[1][nf][1]);
                    mma16816(acc[mf][nf], a[1][mf], b[0][nf][0], b[0][nf][1]);
                }
        }
        __syncthreads();
    }

    // ----------------------------- epilogue --------------------------------
    const int mbase = m0 + wrow * 64;
    const int nbase = n0 + wcol * 32;
    #pragma unroll
    for (int mf = 0; mf < 4; ++mf) {
        #pragma unroll
        for (int nf = 0; nf < 4; ++nf) {
            const int r0  = mbase + mf * 16 + (lane >> 2);
            const int col = nbase + nf * 8 + (lane & 3) * 2;
            #pragma unroll
            for (int h2 = 0; h2 < 2; ++h2) {        // c0c1 (row r0) / c2c3 (r0+8)
                const int row = r0 + h2 * 8;
                const float v0 = acc[mf][nf][h2 * 2 + 0];
                const float v1 = acc[mf][nf][h2 * 2 + 1];
                if (EPI == 0) {
                    C[(size_t)row * Ntot + col]     = v0;
                    C[(size_t)row * Ntot + col + 1] = v1;
                } else if (EPI == 1) {
                    const size_t ix = (size_t)row * Ntot + col;
                    C[ix]     += v0;
                    C[ix + 1] += v1;
                } else if (EPI == 2) {
                    const float x0 = v0 + aux[col];
                    const float x1 = v1 + aux[col + 1];
                    C[(size_t)row * Ntot + col] =
                        fmaxf(x0, 0.f) + log1pf(__expf(-fabsf(x0)));
                    C[(size_t)row * Ntot + col + 1] =
                        fmaxf(x1, 0.f) + log1pf(__expf(-fabsf(x1)));
                } else {
                    if (col < SSMC)     C[(size_t)row * SSMC + col]     = v0;
                    if (col + 1 < SSMC) C[(size_t)row * SSMC + col + 1] = v1;
                    if (col < KPAD) {
                        const float w0 = (col < DTRK) ? v0 : 0.f;
                        const float w1 = (col + 1 < DTRK) ? v1 : 0.f;
                        bf16 a0, b0, a1, b1;
                        fsplit(w0, a0, b0); fsplit(w1, a1, b1);
                        oh[(size_t)row * KPAD + col]     = a0;
                        ol[(size_t)row * KPAD + col]     = b0;
                        oh[(size_t)row * KPAD + col + 1] = a1;
                        ol[(size_t)row * KPAD + col + 1] = b1;
                    }
                }
            }
        }
    }
}

// -------------------------------- launcher ---------------------------------
extern "C" void kernel_launch(void* const* d_in, const int* in_sizes, int n_in,
                              void* d_out, int out_size) {
    (void)in_sizes; (void)n_in; (void)out_size;
    const float* x      = (const float*)d_in[0];
    const float* norm_w = (const float*)d_in[1];
    const float* in_w   = (const float*)d_in[2];
    const float* conv_w = (const float*)d_in[3];
    const float* conv_b = (const float*)d_in[4];
    const float* xw     = (const float*)d_in[5];
    const float* dtw    = (const float*)d_in[6];
    const float* dtb    = (const float*)d_in[7];
    const float* A_log  = (const float*)d_in[8];
    const float* Dsk    = (const float*)d_in[9];
    const float* ow     = (const float*)d_in[10];
    const float* fnw    = (const float*)d_in[11];
    float* out = (float*)d_out;

    float *h, *proj, *u, *ssm, *dt;
    bf16 *hn_h, *hn_l, *u_h, *u_l, *di_h, *di_l, *y_h, *y_l;
    bf16 *wi_h, *wi_l, *wx_h, *wx_l, *wd_h, *wd_l, *wo_h, *wo_l;
    cudaGetSymbolAddress((void**)&h,    g_h);
    cudaGetSymbolAddress((void**)&proj, g_proj);
    cudaGetSymbolAddress((void**)&u,    g_u);
    cudaGetSymbolAddress((void**)&ssm,  g_ssm);
    cudaGetSymbolAddress((void**)&dt,   g_dt);
    cudaGetSymbolAddress((void**)&hn_h, g_hn_h); cudaGetSymbolAddress((void**)&hn_l, g_hn_l);
    cudaGetSymbolAddress((void**)&u_h,  g_u_h);  cudaGetSymbolAddress((void**)&u_l,  g_u_l);
    cudaGetSymbolAddress((void**)&di_h, g_di_h); cudaGetSymbolAddress((void**)&di_l, g_di_l);
    cudaGetSymbolAddress((void**)&y_h,  g_y_h);  cudaGetSymbolAddress((void**)&y_l,  g_y_l);
    cudaGetSymbolAddress((void**)&wi_h, g_wi_h); cudaGetSymbolAddress((void**)&wi_l, g_wi_l);
    cudaGetSymbolAddress((void**)&wx_h, g_wx_h); cudaGetSymbolAddress((void**)&wx_l, g_wx_l);
    cudaGetSymbolAddress((void**)&wd_h, g_wd_h); cudaGetSymbolAddress((void**)&wd_l, g_wd_l);
    cudaGetSymbolAddress((void**)&wo_h, g_wo_h); cudaGetSymbolAddress((void**)&wo_l, g_wo_l);

    cudaFuncSetAttribute(gemm_mma<128, 0>, cudaFuncAttributeMaxDynamicSharedMemorySize, GEMM_DSMEM);
    cudaFuncSetAttribute(gemm_mma<128, 1>, cudaFuncAttributeMaxDynamicSharedMemorySize, GEMM_DSMEM);
    cudaFuncSetAttribute(gemm_mma<128, 2>, cudaFuncAttributeMaxDynamicSharedMemorySize, GEMM_DSMEM);
    cudaFuncSetAttribute(gemm_mma<SSMC, 3>, cudaFuncAttributeMaxDynamicSharedMemorySize, GEMM_DSMEM);

    cudaMemcpyAsync(h, x, sizeof(float) * (size_t)M * DM, cudaMemcpyDeviceToDevice);

    // weight splits (once per call)
    {
        const int n1 = NL * 2 * ED * DM;
        split_arr<<<(n1 + 255) / 256, 256>>>(in_w, wi_h, wi_l, n1);
        const int n2 = NL * SSMC * ED;
        split_arr<<<(n2 + 255) / 256, 256>>>(xw, wx_h, wx_l, n2);
        const int n3 = NL * ED * KPAD;
        split_dtw<<<(n3 + 255) / 256, 256>>>(dtw, wd_h, wd_l);
        const int n4 = NL * DM * ED;
        split_arr<<<(n4 + 255) / 256, 256>>>(ow, wo_h, wo_l, n4);
    }

    const int NE = M * ED;
    for (int l = 0; l < NL; l++) {
        // 1) pre-norm -> split bf16
        rmsnorm_kernel<true><<<M, 256>>>(h, norm_w + l * DM, nullptr, hn_h, hn_l);
        // 2) in_proj: proj[M,3072] = hn @ in_w^T
        gemm_mma<128, 0><<<dim3(2 * ED / 128, M / 128), 256, GEMM_DSMEM>>>(
            hn_h, hn_l, wi_h + (size_t)l * 2 * ED * DM, wi_l + (size_t)l * 2 * ED * DM,
            DM, 2 * ED, proj, nullptr, nullptr, nullptr);
        // 3) causal conv + silu -> u fp32 + split
        conv_silu_kernel<<<(NE + 255) / 256, 256>>>(
            proj, conv_w + l * ED * 4, conv_b + l * ED, u, u_h, u_l);
        // 4) x_proj: ssm[M,80] = u @ xw^T ; also split+pad dt input
        gemm_mma<SSMC, 3><<<dim3(1, M / 128), 256, GEMM_DSMEM>>>(
            u_h, u_l, wx_h + (size_t)l * SSMC * ED, wx_l + (size_t)l * SSMC * ED,
            ED, SSMC, ssm, nullptr, di_h, di_l);
        // 5) dt_proj (+bias, softplus fused): dt[M,1536]
        gemm_mma<128, 2><<<dim3(ED / 128, M / 128), 256, GEMM_DSMEM>>>(
            di_h, di_l, wd_h + (size_t)l * ED * KPAD, wd_l + (size_t)l * ED * KPAD,
            KPAD, ED, dt, dtb + l * ED, nullptr, nullptr);
        // 6) selective scan + Dskip + gate -> y split
        scan_kernel<<<dim3(ED / 32, BB), 128>>>(
            dt, u, ssm, proj, A_log + (size_t)l * ED * NS, Dsk + l * ED, y_h, y_l);
        // 7) out_proj + residual: h += y @ ow^T
        gemm_mma<128, 1><<<dim3(DM / 128, M / 128), 256, GEMM_DSMEM>>>(
            y_h, y_l, wo_h + (size_t)l * DM * ED, wo_l + (size_t)l * DM * ED,
            ED, DM, h, nullptr, nullptr, nullptr);
    }
    rmsnorm_kernel<false><<<M, 256>>>(h, fnw, out, nullptr, nullptr);
}

// round 8
// speedup vs baseline: 1.3212x; 1.0094x over previous
#include <cuda_runtime.h>
#include <cuda_bf16.h>
#include <math.h>
#include <stdint.h>

typedef __nv_bfloat16 bf16;

namespace {
constexpr int NL = 8, DM = 768, ED = 1536, NS = 16, DTRK = 48, BB = 2, LL = 2048;
constexpr int M    = BB * LL;          // 4096
constexpr int SSMC = DTRK + 2 * NS;    // 80
constexpr int KPAD = 64;               // padded dt rank
constexpr float EPS = 1e-5f;
// GEMM tiling: 128x128 tile, BK=32, 3 stages, 512 threads (16 warps, 4x4)
constexpr int RSB   = 80;              // SMEM row stride bytes (64 data + 16 pad)
constexpr int TILEB = 128 * RSB;       // 10240 B per split tile
constexpr int STB   = 4 * TILEB;       // Ah,Al,Bh,Bl = 40960 B
constexpr int GEMM_DSMEM = 3 * STB;    // 122880 B
}

// ------------------------- scratch (static device) -------------------------
__device__ float g_h   [M * DM];
__device__ float g_proj[M * 2 * ED];
__device__ float g_u   [M * ED];
__device__ float g_ssm [M * SSMC];
__device__ float g_dt  [M * ED];
__device__ __align__(16) bf16 g_hn_h[M * DM],  g_hn_l[M * DM];
__device__ __align__(16) bf16 g_u_h [M * ED],  g_u_l [M * ED];
__device__ __align__(16) bf16 g_di_h[M * KPAD], g_di_l[M * KPAD];
__device__ __align__(16) bf16 g_y_h [M * ED],  g_y_l [M * ED];
__device__ __align__(16) bf16 g_wi_h[NL * 2 * ED * DM], g_wi_l[NL * 2 * ED * DM];
__device__ __align__(16) bf16 g_wx_h[NL * SSMC * ED],   g_wx_l[NL * SSMC * ED];
__device__ __align__(16) bf16 g_wd_h[NL * ED * KPAD],   g_wd_l[NL * ED * KPAD];
__device__ __align__(16) bf16 g_wo_h[NL * DM * ED],     g_wo_l[NL * DM * ED];

// ------------------------------ tiny helpers -------------------------------
__device__ __forceinline__ void fsplit(float v, bf16& h, bf16& l) {
    h = __float2bfloat16(v);
    l = __float2bfloat16(v - __bfloat162float(h));
}
__device__ __forceinline__ uint32_t smem_u32(const void* p) {
    return (uint32_t)__cvta_generic_to_shared(p);
}
__device__ __forceinline__ void cp16(uint32_t dst, const bf16* src) {
    asm volatile("cp.async.cg.shared.global [%0], [%1], 16;"
                 :: "r"(dst), "l"(src));
}
__device__ __forceinline__ void ldsm_x4(uint32_t* r, uint32_t addr) {
    asm volatile("ldmatrix.sync.aligned.m8n8.x4.shared.b16 {%0,%1,%2,%3}, [%4];"
                 : "=r"(r[0]), "=r"(r[1]), "=r"(r[2]), "=r"(r[3]) : "r"(addr));
}
__device__ __forceinline__ void mma16816(float* d, const uint32_t* a,
                                         uint32_t b0, uint32_t b1) {
    asm volatile(
        "mma.sync.aligned.m16n8k16.row.col.f32.bf16.bf16.f32 "
        "{%0,%1,%2,%3}, {%4,%5,%6,%7}, {%8,%9}, {%0,%1,%2,%3};"
        : "+f"(d[0]), "+f"(d[1]), "+f"(d[2]), "+f"(d[3])
        : "r"(a[0]), "r"(a[1]), "r"(a[2]), "r"(a[3]), "r"(b0), "r"(b1));
}

// ----------------------------- split converts ------------------------------
__global__ void split_arr(const float* __restrict__ w, bf16* __restrict__ h,
                          bf16* __restrict__ l, int n) {
    int i = blockIdx.x * 256 + threadIdx.x;
    if (i < n) { bf16 a, b; fsplit(w[i], a, b); h[i] = a; l[i] = b; }
}
// fused split of x_proj, dt_proj(padded to 64), out_proj weights
__global__ void split_rest(const float* __restrict__ xw,  bf16* __restrict__ xh, bf16* __restrict__ xl,
                           const float* __restrict__ dtw, bf16* __restrict__ dh, bf16* __restrict__ dl,
                           const float* __restrict__ ow,  bf16* __restrict__ oh, bf16* __restrict__ ol) {
    constexpr int N2 = NL * SSMC * ED;     // 983040
    constexpr int N3 = NL * ED * KPAD;     // 786432
    constexpr int N4 = NL * DM * ED;       // 9437184
    int i = blockIdx.x * 256 + threadIdx.x;
    if (i < N2) {
        bf16 a, b; fsplit(xw[i], a, b); xh[i] = a; xl[i] = b;
    } else if (i < N2 + N3) {
        int j = i - N2;
        int r = j & 63, e = j >> 6;
        float v = (r < DTRK) ? dtw[e * DTRK + r] : 0.f;
        bf16 a, b; fsplit(v, a, b); dh[j] = a; dl[j] = b;
    } else if (i < N2 + N3 + N4) {
        int j = i - N2 - N3;
        bf16 a, b; fsplit(ow[j], a, b); oh[j] = a; ol[j] = b;
    }
}

// ------------------------------- RMSNorm -----------------------------------
template <bool SPLIT>
__global__ void rmsnorm_kernel(const float* __restrict__ h,
                               const float* __restrict__ w,
                               float* __restrict__ outf,
                               bf16* __restrict__ outh, bf16* __restrict__ outl) {
    const int m = blockIdx.x;
    const float* row = h + (size_t)m * DM;
    float s = 0.f;
    for (int i = threadIdx.x; i < DM; i += 256) { float v = row[i]; s = fmaf(v, v, s); }
    #pragma unroll
    for (int o = 16; o; o >>= 1) s += __shfl_xor_sync(0xffffffffu, s, o);
    __shared__ float red[8];
    if ((threadIdx.x & 31) == 0) red[threadIdx.x >> 5] = s;
    __syncthreads();
    if (threadIdx.x == 0) {
        float t = 0.f;
        #pragma unroll
        for (int i = 0; i < 8; i++) t += red[i];
        red[0] = rsqrtf(t * (1.0f / DM) + EPS);
    }
    __syncthreads();
    const float inv = red[0];
    for (int i = threadIdx.x; i < DM; i += 256) {
        float v = row[i] * inv * w[i];
        if (SPLIT) {
            bf16 a, b; fsplit(v, a, b);
            outh[(size_t)m * DM + i] = a; outl[(size_t)m * DM + i] = b;
        } else {
            outf[(size_t)m * DM + i] = v;
        }
    }
}

// ------------------------ causal depthwise conv + silu ---------------------
__global__ void conv_silu_kernel(const float* __restrict__ proj,
                                 const float* __restrict__ cw,
                                 const float* __restrict__ cb,
                                 float* __restrict__ u,
                                 bf16* __restrict__ uh, bf16* __restrict__ ul) {
    const int idx = blockIdx.x * blockDim.x + threadIdx.x;
    if (idx >= M * ED) return;
    const int e = idx % ED;
    const int m = idx / ED;
    const int t = m % LL;
    const float w0 = cw[e * 4 + 0], w1 = cw[e * 4 + 1];
    const float w2 = cw[e * 4 + 2], w3 = cw[e * 4 + 3];
    const float* col = proj + (size_t)m * (2 * ED) + e;
    float acc = cb[e];
    acc = fmaf(w3, col[0], acc);
    if (t >= 1) acc = fmaf(w2, col[-(ptrdiff_t)(2 * ED)], acc);
    if (t >= 2) acc = fmaf(w1, col[-(ptrdiff_t)(4 * ED)], acc);
    if (t >= 3) acc = fmaf(w0, col[-(ptrdiff_t)(6 * ED)], acc);
    float v = acc / (1.f + __expf(-acc));
    u[idx] = v;
    bf16 a, b; fsplit(v, a, b);
    uh[idx] = a; ul[idx] = b;
}

// ------------------------------ selective scan -----------------------------
namespace { constexpr int SCAN_T = 16; }

__global__ void __launch_bounds__(128)
scan_kernel(const float* __restrict__ dt, const float* __restrict__ u,
            const float* __restrict__ ssm, const float* __restrict__ proj,
            const float* __restrict__ A_log_l, const float* __restrict__ Dsk_l,
            bf16* __restrict__ yh, bf16* __restrict__ yl) {
    const int b  = blockIdx.y;
    const int e0 = blockIdx.x * 32;
    const int tx = threadIdx.x;
    const int el = tx >> 2, sub = tx & 3;
    const int e  = e0 + el;

    __shared__ float sdt[SCAN_T][32];
    __shared__ float su [SCAN_T][32];
    __shared__ float sg [SCAN_T][32];
    __shared__ float sB [SCAN_T][NS];
    __shared__ float sC [SCAN_T][NS];

    float Ac[4];
    #pragma unroll
    for (int j = 0; j < 4; j++) Ac[j] = -expf(A_log_l[e * NS + sub * 4 + j]);
    const float Dk = Dsk_l[e];
    float st[4] = {0.f, 0.f, 0.f, 0.f};

    for (int t0 = 0; t0 < LL; t0 += SCAN_T) {
        __syncthreads();
        for (int i = tx; i < SCAN_T * 32; i += 128) {
            const int t = i >> 5, c = i & 31;
            const size_t m = (size_t)(b * LL + t0 + t);
            sdt[t][c] = dt[m * ED + e0 + c];
            su [t][c] = u [m * ED + e0 + c];
            sg [t][c] = proj[m * (2 * ED) + ED + e0 + c];
        }
        for (int i = tx; i < SCAN_T * NS; i += 128) {
            const int t = i >> 4, n = i & (NS - 1);
            const size_t base = (size_t)(b * LL + t0 + t) * SSMC;
            sB[t][n] = ssm[base + DTRK + n];
            sC[t][n] = ssm[base + DTRK + NS + n];
        }
        __syncthreads();
        #pragma unroll 4
        for (int t = 0; t < SCAN_T; t++) {
            const float dtv = sdt[t][el];
            const float uv  = su[t][el];
            const float dtu = dtv * uv;
            float yv = 0.f;
            #pragma unroll
            for (int j = 0; j < 4; j++) {
                const float dA = __expf(dtv * Ac[j]);
                st[j] = fmaf(st[j], dA, dtu * sB[t][sub * 4 + j]);
                yv = fmaf(st[j], sC[t][sub * 4 + j], yv);
            }
            yv += __shfl_xor_sync(0xffffffffu, yv, 1);
            yv += __shfl_xor_sync(0xffffffffu, yv, 2);
            if (sub == 0) {
                const float g   = sg[t][el];
                const float sil = g / (1.f + __expf(-g));
                const float val = (yv + uv * Dk) * sil;
                const size_t oi = ((size_t)(b * LL + t0 + t)) * ED + e;
                bf16 a, bl; fsplit(val, a, bl);
                yh[oi] = a; yl[oi] = bl;
            }
        }
    }
}

// ------------------- tensor-core split-bf16 GEMM (mma.sync) ----------------
// C[M,Ntot] = A[M,K] x B[N,K]^T via AhBh + AhBl + AlBh.
// 128x128 tile/CTA, BK=32, 3-stage cp.async, 512 threads = 16 warps (4x4),
// warp tile 32x32, one __syncthreads per K-stage, product-major mma order.
// EPI: 0 = store fp32; 1 = C += result (residual, in place);
//      2 = softplus(result + aux[col]);  3 = x_proj (ssm fp32 + dt-in split)
template <int NB, int EPI>
__global__ void __launch_bounds__(512, 1)
gemm_mma(const bf16* __restrict__ Ah, const bf16* __restrict__ Al,
         const bf16* __restrict__ Bh, const bf16* __restrict__ Bl,
         int K, int Ntot,
         float* __restrict__ C, const float* __restrict__ aux,
         bf16* __restrict__ oh, bf16* __restrict__ ol) {
    extern __shared__ char dsm[];
    const uint32_t base = smem_u32(dsm);
    const int tid = threadIdx.x, wid = tid >> 5, lane = tid & 31;
    const int m0 = blockIdx.y * 128, n0 = blockIdx.x * 128;
    const int wrow = wid >> 2, wcol = wid & 3;       // 4x4 warps

    float acc[2][4][4];                               // mf x nf x c
    #pragma unroll
    for (int i = 0; i < 2; i++)
        #pragma unroll
        for (int j = 0; j < 4; j++)
            #pragma unroll
            for (int c = 0; c < 4; c++) acc[i][j][c] = 0.f;

    const int S = K >> 5;   // k-stages of 32

    auto load_stage = [&](int st) {
        const int k0 = st << 5;
        const uint32_t sb = base + (st % 3) * STB;
        #pragma unroll
        for (int it = 0; it < 2; ++it) {    // A: 2 splits x 128 rows x 4 x16B
            int i = tid + it * 512;
            int split = i >> 9;
            int r = (i >> 2) & 127;
            int c = i & 3;
            const bf16* src = (split ? Al : Ah) + (size_t)(m0 + r) * K + k0 + c * 8;
            cp16(sb + split * TILEB + r * RSB + c * 16, src);
        }
        #pragma unroll
        for (int it = 0; it < 2; ++it) {    // B
            int i = tid + it * 512;
            int split = i >> 9;
            int r = (i >> 2) & 127;
            int c = i & 3;
            if (NB == 128 || r < NB) {
                const bf16* src = (split ? Bl : Bh) + (size_t)(n0 + r) * K + k0 + c * 8;
                cp16(sb + 2 * TILEB + split * TILEB + r * RSB + c * 16, src);
            }
        }
    };

    // lane-invariant ldmatrix offsets (bytes within a stage)
    uint32_t aoff[2][2], boff[2][2];
    {
        const int ar = wrow * 32 + (lane & 15);
        const int ak = (lane >> 4) * 16;
        #pragma unroll
        for (int sp = 0; sp < 2; ++sp)
            #pragma unroll
            for (int mf = 0; mf < 2; ++mf)
                aoff[sp][mf] = sp * TILEB + (ar + mf * 16) * RSB + ak;
        const int br = wcol * 32 + (lane & 7) + ((lane >> 4) << 3);
        const int bk = ((lane >> 3) & 1) * 16;
        #pragma unroll
        for (int sp = 0; sp < 2; ++sp)
            #pragma unroll
            for (int nf2 = 0; nf2 < 2; ++nf2)
                boff[sp][nf2] = 2 * TILEB + sp * TILEB + (br + nf2 * 16) * RSB + bk;
    }

    // prologue: stages 0,1
    for (int p = 0; p < 2; ++p) {
        if (p < S) load_stage(p);
        asm volatile("cp.async.commit_group;");
    }

    for (int s = 0; s < S; ++s) {
        asm volatile("cp.async.wait_group 1;");
        __syncthreads();
        if (s + 2 < S) load_stage(s + 2);
        asm volatile("cp.async.commit_group;");

        const uint32_t sb = base + (s % 3) * STB;
        #pragma unroll
        for (int ks = 0; ks < 2; ++ks) {
            const uint32_t kb = ks * 32;
            uint32_t a[2][2][4];
            #pragma unroll
            for (int sp = 0; sp < 2; ++sp)
                #pragma unroll
                for (int mf = 0; mf < 2; ++mf)
                    ldsm_x4(a[sp][mf], sb + aoff[sp][mf] + kb);
            uint32_t b[2][4][2];
            #pragma unroll
            for (int sp = 0; sp < 2; ++sp)
                #pragma unroll
                for (int nf2 = 0; nf2 < 2; ++nf2) {
                    uint32_t r[4];
                    ldsm_x4(r, sb + boff[sp][nf2] + kb);
                    b[sp][2 * nf2][0]     = r[0];
                    b[sp][2 * nf2][1]     = r[1];
                    b[sp][2 * nf2 + 1][0] = r[2];
                    b[sp][2 * nf2 + 1][1] = r[3];
                }
            // product-major: hh, hl, lh — each acc touched once per sweep
            #pragma unroll
            for (int p = 0; p < 3; ++p) {
                const int pa = (p == 2) ? 1 : 0;
                const int pb = (p == 1) ? 1 : 0;
                #pragma unroll
                for (int mf = 0; mf < 2; ++mf)
                    #pragma unroll
                    for (int nf = 0; nf < 4; ++nf)
                        mma16816(acc[mf][nf], a[pa][mf],
                                 b[pb][nf][0], b[pb][nf][1]);
            }
        }
    }
    // drain any in-flight groups before exit
    asm volatile("cp.async.wait_group 0;");

    // ----------------------------- epilogue --------------------------------
    const int mbase = m0 + wrow * 32;
    const int nbase = n0 + wcol * 32;
    #pragma unroll
    for (int mf = 0; mf < 2; ++mf) {
        #pragma unroll
        for (int nf = 0; nf < 4; ++nf) {
            const int r0  = mbase + mf * 16 + (lane >> 2);
            const int col = nbase + nf * 8 + (lane & 3) * 2;
            #pragma unroll
            for (int h2 = 0; h2 < 2; ++h2) {
                const int row = r0 + h2 * 8;
                const float v0 = acc[mf][nf][h2 * 2 + 0];
                const float v1 = acc[mf][nf][h2 * 2 + 1];
                if (EPI == 0) {
                    C[(size_t)row * Ntot + col]     = v0;
                    C[(size_t)row * Ntot + col + 1] = v1;
                } else if (EPI == 1) {
                    const size_t ix = (size_t)row * Ntot + col;
                    C[ix]     += v0;
                    C[ix + 1] += v1;
                } else if (EPI == 2) {
                    const float x0 = v0 + aux[col];
                    const float x1 = v1 + aux[col + 1];
                    C[(size_t)row * Ntot + col] =
                        fmaxf(x0, 0.f) + log1pf(__expf(-fabsf(x0)));
                    C[(size_t)row * Ntot + col + 1] =
                        fmaxf(x1, 0.f) + log1pf(__expf(-fabsf(x1)));
                } else {
                    if (col < SSMC)     C[(size_t)row * SSMC + col]     = v0;
                    if (col + 1 < SSMC) C[(size_t)row * SSMC + col + 1] = v1;
                    if (col < KPAD) {
                        const float w0 = (col < DTRK) ? v0 : 0.f;
                        const float w1 = (col + 1 < DTRK) ? v1 : 0.f;
                        bf16 a0, b0, a1, b1;
                        fsplit(w0, a0, b0); fsplit(w1, a1, b1);
                        oh[(size_t)row * KPAD + col]     = a0;
                        ol[(size_t)row * KPAD + col]     = b0;
                        oh[(size_t)row * KPAD + col + 1] = a1;
                        ol[(size_t)row * KPAD + col + 1] = b1;
                    }
                }
            }
        }
    }
}

// -------------------------------- launcher ---------------------------------
extern "C" void kernel_launch(void* const* d_in, const int* in_sizes, int n_in,
                              void* d_out, int out_size) {
    (void)in_sizes; (void)n_in; (void)out_size;
    const float* x      = (const float*)d_in[0];
    const float* norm_w = (const float*)d_in[1];
    const float* in_w   = (const float*)d_in[2];
    const float* conv_w = (const float*)d_in[3];
    const float* conv_b = (const float*)d_in[4];
    const float* xw     = (const float*)d_in[5];
    const float* dtw    = (const float*)d_in[6];
    const float* dtb    = (const float*)d_in[7];
    const float* A_log  = (const float*)d_in[8];
    const float* Dsk    = (const float*)d_in[9];
    const float* ow     = (const float*)d_in[10];
    const float* fnw    = (const float*)d_in[11];
    float* out = (float*)d_out;

    float *h, *proj, *u, *ssm, *dt;
    bf16 *hn_h, *hn_l, *u_h, *u_l, *di_h, *di_l, *y_h, *y_l;
    bf16 *wi_h, *wi_l, *wx_h, *wx_l, *wd_h, *wd_l, *wo_h, *wo_l;
    cudaGetSymbolAddress((void**)&h,    g_h);
    cudaGetSymbolAddress((void**)&proj, g_proj);
    cudaGetSymbolAddress((void**)&u,    g_u);
    cudaGetSymbolAddress((void**)&ssm,  g_ssm);
    cudaGetSymbolAddress((void**)&dt,   g_dt);
    cudaGetSymbolAddress((void**)&hn_h, g_hn_h); cudaGetSymbolAddress((void**)&hn_l, g_hn_l);
    cudaGetSymbolAddress((void**)&u_h,  g_u_h);  cudaGetSymbolAddress((void**)&u_l,  g_u_l);
    cudaGetSymbolAddress((void**)&di_h, g_di_h); cudaGetSymbolAddress((void**)&di_l, g_di_l);
    cudaGetSymbolAddress((void**)&y_h,  g_y_h);  cudaGetSymbolAddress((void**)&y_l,  g_y_l);
    cudaGetSymbolAddress((void**)&wi_h, g_wi_h); cudaGetSymbolAddress((void**)&wi_l, g_wi_l);
    cudaGetSymbolAddress((void**)&wx_h, g_wx_h); cudaGetSymbolAddress((void**)&wx_l, g_wx_l);
    cudaGetSymbolAddress((void**)&wd_h, g_wd_h); cudaGetSymbolAddress((void**)&wd_l, g_wd_l);
    cudaGetSymbolAddress((void**)&wo_h, g_wo_h); cudaGetSymbolAddress((void**)&wo_l, g_wo_l);

    cudaFuncSetAttribute(gemm_mma<128, 0>, cudaFuncAttributeMaxDynamicSharedMemorySize, GEMM_DSMEM);
    cudaFuncSetAttribute(gemm_mma<128, 1>, cudaFuncAttributeMaxDynamicSharedMemorySize, GEMM_DSMEM);
    cudaFuncSetAttribute(gemm_mma<128, 2>, cudaFuncAttributeMaxDynamicSharedMemorySize, GEMM_DSMEM);
    cudaFuncSetAttribute(gemm_mma<SSMC, 3>, cudaFuncAttributeMaxDynamicSharedMemorySize, GEMM_DSMEM);

    cudaMemcpyAsync(h, x, sizeof(float) * (size_t)M * DM, cudaMemcpyDeviceToDevice);

    // weight splits — 2 launches so kernel slot #4 is the in_proj GEMM (ncu)
    {
        const int n1 = NL * 2 * ED * DM;
        split_arr<<<(n1 + 255) / 256, 256>>>(in_w, wi_h, wi_l, n1);
        const int nrest = NL * SSMC * ED + NL * ED * KPAD + NL * DM * ED;
        split_rest<<<(nrest + 255) / 256, 256>>>(xw, wx_h, wx_l,
                                                 dtw, wd_h, wd_l,
                                                 ow, wo_h, wo_l);
    }

    const int NE = M * ED;
    for (int l = 0; l < NL; l++) {
        // 1) pre-norm -> split bf16
        rmsnorm_kernel<true><<<M, 256>>>(h, norm_w + l * DM, nullptr, hn_h, hn_l);
        // 2) in_proj: proj[M,3072] = hn @ in_w^T
        gemm_mma<128, 0><<<dim3(2 * ED / 128, M / 128), 512, GEMM_DSMEM>>>(
            hn_h, hn_l, wi_h + (size_t)l * 2 * ED * DM, wi_l + (size_t)l * 2 * ED * DM,
            DM, 2 * ED, proj, nullptr, nullptr, nullptr);
        // 3) causal conv + silu -> u fp32 + split
        conv_silu_kernel<<<(NE + 255) / 256, 256>>>(
            proj, conv_w + l * ED * 4, conv_b + l * ED, u, u_h, u_l);
        // 4) x_proj: ssm[M,80] = u @ xw^T ; also split+pad dt input
        gemm_mma<SSMC, 3><<<dim3(1, M / 128), 512, GEMM_DSMEM>>>(
            u_h, u_l, wx_h + (size_t)l * SSMC * ED, wx_l + (size_t)l * SSMC * ED,
            ED, SSMC, ssm, nullptr, di_h, di_l);
        // 5) dt_proj (+bias, softplus fused): dt[M,1536]
        gemm_mma<128, 2><<<dim3(ED / 128, M / 128), 512, GEMM_DSMEM>>>(
            di_h, di_l, wd_h + (size_t)l * ED * KPAD, wd_l + (size_t)l * ED * KPAD,
            KPAD, ED, dt, dtb + l * ED, nullptr, nullptr);
        // 6) selective scan + Dskip + gate -> y split
        scan_kernel<<<dim3(ED / 32, BB), 128>>>(
            dt, u, ssm, proj, A_log + (size_t)l * ED * NS, Dsk + l * ED, y_h, y_l);
        // 7) out_proj + residual: h += y @ ow^T
        gemm_mma<128, 1><<<dim3(DM / 128, M / 128), 512, GEMM_DSMEM>>>(
            y_h, y_l, wo_h + (size_t)l * DM * ED, wo_l + (size_t)l * DM * ED,
            ED, DM, h, nullptr, nullptr, nullptr);
    }
    rmsnorm_kernel<false><<<M, 256>>>(h, fnw, out, nullptr, nullptr);
}